// round 16
// baseline (speedup 1.0000x reference)
#include <cuda_runtime.h>

// MSAColumnGlobalAttention: B=1, s=1024, i=512, c=8, h=8
// R14 structure (proven 37.3us) minus the memcpyToSymbol node:
// Kernel A (4 columns/CTA, 512 thr, grid 128, COALESCED): pass1 LN sums ->
//   xbar -> qk (gamma-folded); pass2 re-read m (L2-hot), e' stored coalesced,
//   0.5/sum -> g_rcp. CTA 0 repacks streaming weights into g_stage.
// Kernel B: same math as the 25us control, but weights read straight from
//   g_stage via warp-uniform LDG.128 (L1-resident broadcast) - no constant
//   copy node, only 2 graph nodes total.

#define LN_EPS 1e-5f
#define I_DIM 512
#define S_DIM 1024
#define A_THREADS 512
#define A_NWARP (A_THREADS / 32)
#define CPG 4                      // columns per CTA
#define NSTRAND (A_THREADS / CPG)  // 128 s-strands
#define ROWS_PT (S_DIM / NSTRAND)  // 8 rows per thread
#define QK_PAD 72                  // conflict-free stride for sQKg
#define B_THREADS 256

struct WeightsB {
    float Wv2[64];
    float Wg2[512];   // pairs over h, PRE-SCALED by 0.5
    float WoP[512];   // pairs over h / co
    float Bo[8];
    float Gamma[8];
    float Beta[8];
};

__device__ WeightsB g_stage;
__device__ float g_w[S_DIM * I_DIM * 8];    // e' = exp(xn . (gamma*qk))
__device__ float g_rcp[I_DIM * 8];          // 0.5 / sum_t e'

// ---- f32x2 helpers ----
__device__ __forceinline__ float2 fma2(float2 a, float2 b, float2 c) {
    unsigned long long ra = *reinterpret_cast<unsigned long long*>(&a);
    unsigned long long rb = *reinterpret_cast<unsigned long long*>(&b);
    unsigned long long rc = *reinterpret_cast<unsigned long long*>(&c);
    unsigned long long rd;
    asm("fma.rn.f32x2 %0, %1, %2, %3;" : "=l"(rd) : "l"(ra), "l"(rb), "l"(rc));
    return *reinterpret_cast<float2*>(&rd);
}
__device__ __forceinline__ float2 mul2(float2 a, float2 b) {
    unsigned long long ra = *reinterpret_cast<unsigned long long*>(&a);
    unsigned long long rb = *reinterpret_cast<unsigned long long*>(&b);
    unsigned long long rd;
    asm("mul.rn.f32x2 %0, %1, %2;" : "=l"(rd) : "l"(ra), "l"(rb));
    return *reinterpret_cast<float2*>(&rd);
}
__device__ __forceinline__ float2 dup(float x) { return make_float2(x, x); }
__device__ __forceinline__ float2 lo2(float4 w) { return make_float2(w.x, w.y); }
__device__ __forceinline__ float2 hi2(float4 w) { return make_float2(w.z, w.w); }

__device__ __forceinline__ float tanh_apx(float x) {
    float y; asm("tanh.approx.f32 %0, %1;" : "=f"(y) : "f"(x)); return y;
}

#define PAIRDOT8(acc, xd, w0, w1, w2, w3)            \
    acc = mul2(xd[0], lo2(w0));                      \
    acc = fma2(xd[1], hi2(w0), acc);                 \
    acc = fma2(xd[2], lo2(w1), acc);                 \
    acc = fma2(xd[3], hi2(w1), acc);                 \
    acc = fma2(xd[4], lo2(w2), acc);                 \
    acc = fma2(xd[5], hi2(w2), acc);                 \
    acc = fma2(xd[6], lo2(w3), acc);                 \
    acc = fma2(xd[7], hi2(w3), acc);

// ============================ Kernel A (R14, unchanged) ============================
__global__ __launch_bounds__(A_THREADS)
void msa_attn_weights_kernel(const float* __restrict__ m,
                             const float* __restrict__ gamma,
                             const float* __restrict__ beta,
                             const float* __restrict__ wq,
                             const float* __restrict__ wk,
                             const float* __restrict__ wv,
                             const float* __restrict__ wg,
                             const float* __restrict__ wo,
                             const float* __restrict__ bo)
{
    const int i0     = blockIdx.x * CPG;
    const int tid    = threadIdx.x;
    const int lane   = tid & 31;
    const int il     = tid & (CPG - 1);      // column within group
    const int strand = tid >> 2;             // 0..127
    const int warp   = tid >> 5;
    const int i      = i0 + il;

    __shared__ float sWq[512];
    __shared__ float sWk[64];
    __shared__ float sRed[A_NWARP][CPG][8];
    __shared__ float sXbar[CPG][8];
    __shared__ float sQKg[CPG][QK_PAD];       // qk * gamma, padded stride 72

    sWq[tid] = wq[tid];
    if (tid < 64) sWk[tid] = wk[tid];

    // CTA 0 repacks streaming weights (overlapped with other CTAs' work)
    if (blockIdx.x == 0) {
        const int row = tid >> 3, j = tid & 7;
        const int h = row >> 3, c = row & 7;
        g_stage.Wg2[((h >> 1) * 8 + c) * 16 + (j >> 1) * 4 + (j & 1) * 2 + (h & 1)] = 0.5f * wg[tid];
        const int co = tid >> 6, idx = tid & 63;
        const int hh = idx >> 3, cc = idx & 7;
        g_stage.WoP[(((hh >> 1) * 8 + cc) * 4 + (co >> 1)) * 4 + (co & 1) * 2 + (hh & 1)] = wo[tid];
        if (tid < 64) {
            const int c2 = tid >> 3, j2 = tid & 7;
            g_stage.Wv2[(c2 >> 1) * 16 + (j2 >> 1) * 4 + (j2 & 1) * 2 + (c2 & 1)] = wv[tid];
        }
        if (tid < 8) {
            g_stage.Bo[tid]    = bo[tid];
            g_stage.Gamma[tid] = gamma[tid];
            g_stage.Beta[tid]  = beta[tid];
        }
    }

    // ---- PASS 1: LN sums over this thread's 8 rows (xn transient) ----
    float acc[8];
#pragma unroll
    for (int c = 0; c < 8; c++) acc[c] = 0.f;

#pragma unroll
    for (int r = 0; r < ROWS_PT; r++) {
        const int s = strand + r * NSTRAND;
        const size_t gid = (size_t)s * I_DIM + i;
        const float4* p = reinterpret_cast<const float4*>(m + gid * 8);
        float4 a0 = p[0];
        float4 a1 = p[1];
        float xr[8] = {a0.x, a0.y, a0.z, a0.w, a1.x, a1.y, a1.z, a1.w};
        float mean = 0.f;
#pragma unroll
        for (int c = 0; c < 8; c++) mean += xr[c];
        mean *= 0.125f;
        float var = 0.f;
#pragma unroll
        for (int c = 0; c < 8; c++) { float d = xr[c] - mean; var = fmaf(d, d, var); }
        var *= 0.125f;
        const float rstd = rsqrtf(var + LN_EPS);
#pragma unroll
        for (int c = 0; c < 8; c++)
            acc[c] = fmaf(xr[c] - mean, rstd, acc[c]);
    }

    // reduce over strands sharing il within warp: shfl 4, 8, 16
#pragma unroll
    for (int c = 0; c < 8; c++) {
        acc[c] += __shfl_xor_sync(0xffffffffu, acc[c], 4);
        acc[c] += __shfl_xor_sync(0xffffffffu, acc[c], 8);
        acc[c] += __shfl_xor_sync(0xffffffffu, acc[c], 16);
    }
    if (lane < CPG) {
#pragma unroll
        for (int c = 0; c < 8; c++) sRed[warp][lane][c] = acc[c];
    }
    __syncthreads();
    if (tid < CPG * 8) {
        const int jl = tid >> 3, c = tid & 7;
        float s = sRed[0][jl][c];
#pragma unroll
        for (int w = 1; w < A_NWARP; w++) s += sRed[w][jl][c];
        // xbar = gamma * sum(xn) + 1024 * beta   (exact)
        sXbar[jl][c] = fmaf(__ldg(gamma + c), s, 1024.f * __ldg(beta + c));
    }
    __syncthreads();

    // qk for 4 columns: tid < 256 -> (il2, h, j)
    if (tid < CPG * 64) {
        const int il2 = tid >> 6;
        const int hj  = tid & 63;
        const int h = hj >> 3, j = hj & 7;
        float qk = 0.f;
#pragma unroll
        for (int c = 0; c < 8; c++) {
            float q = 0.f;
#pragma unroll
            for (int d = 0; d < 8; d++)
                q = fmaf(sXbar[il2][d], sWq[(h * 8 + c) * 8 + d], q);
            qk = fmaf(q, sWk[c * 8 + j], qk);
        }
        const float qscale = (1.f / 1024.f) * 0.35355339059327373f;
        sQKg[il2][h * 8 + j] = qk * qscale * __ldg(gamma + j);
    }
    __syncthreads();

    // ---- PASS 2: re-read m (L2-hot), recompute LN, e' -> store, sum ----
    float hred[8];
#pragma unroll
    for (int h = 0; h < 8; h++) hred[h] = 0.f;

#pragma unroll
    for (int r = 0; r < ROWS_PT; r++) {
        const int s = strand + r * NSTRAND;
        const size_t gid = (size_t)s * I_DIM + i;
        const float4* p = reinterpret_cast<const float4*>(m + gid * 8);
        float4 a0 = p[0];
        float4 a1 = p[1];
        float xn[8] = {a0.x, a0.y, a0.z, a0.w, a1.x, a1.y, a1.z, a1.w};
        float mean = 0.f;
#pragma unroll
        for (int c = 0; c < 8; c++) mean += xn[c];
        mean *= 0.125f;
        float var = 0.f;
#pragma unroll
        for (int c = 0; c < 8; c++) { float d = xn[c] - mean; var = fmaf(d, d, var); }
        var *= 0.125f;
        const float rstd = rsqrtf(var + LN_EPS);
#pragma unroll
        for (int c = 0; c < 8; c++)
            xn[c] = (xn[c] - mean) * rstd;

        float e[8];
#pragma unroll
        for (int h = 0; h < 8; h++) {
            const float4 qa = *reinterpret_cast<const float4*>(&sQKg[il][h * 8]);
            const float4 qb = *reinterpret_cast<const float4*>(&sQKg[il][h * 8 + 4]);
            float a = xn[0] * qa.x, b = xn[1] * qa.y;
            a = fmaf(xn[2], qa.z, a);  b = fmaf(xn[3], qa.w, b);
            a = fmaf(xn[4], qb.x, a);  b = fmaf(xn[5], qb.y, b);
            a = fmaf(xn[6], qb.z, a);  b = fmaf(xn[7], qb.w, b);
            e[h] = __expf(a + b);
            hred[h] += e[h];
        }
        float4* pw = reinterpret_cast<float4*>(&g_w[gid * 8]);
        pw[0] = make_float4(e[0], e[1], e[2], e[3]);
        pw[1] = make_float4(e[4], e[5], e[6], e[7]);
    }

#pragma unroll
    for (int h = 0; h < 8; h++) {
        hred[h] += __shfl_xor_sync(0xffffffffu, hred[h], 4);
        hred[h] += __shfl_xor_sync(0xffffffffu, hred[h], 8);
        hred[h] += __shfl_xor_sync(0xffffffffu, hred[h], 16);
    }
    if (lane < CPG) {
#pragma unroll
        for (int h = 0; h < 8; h++) sRed[warp][lane][h] = hred[h];
    }
    __syncthreads();
    if (tid < CPG * 8) {
        const int jl = tid >> 3, h = tid & 7;
        float s = sRed[0][jl][h];
#pragma unroll
        for (int w = 1; w < A_NWARP; w++) s += sRed[w][jl][h];
        g_rcp[(i0 + jl) * 8 + h] = __fdividef(0.5f, s);
    }
}

// ============================ Kernel B (weights via uniform LDG) ============================
__global__ __launch_bounds__(B_THREADS, 4)
void msa_stream_kernel(const float* __restrict__ m,
                       float* __restrict__ out)
{
    const size_t gid = (size_t)blockIdx.x * B_THREADS + threadIdx.x;  // = s*512 + i
    const int i = (int)(gid & (I_DIM - 1));

    const float4* __restrict__ Wv2p = reinterpret_cast<const float4*>(g_stage.Wv2);
    const float4* __restrict__ Wg2p = reinterpret_cast<const float4*>(g_stage.Wg2);
    const float4* __restrict__ WoPp = reinterpret_cast<const float4*>(g_stage.WoP);

    float gam[8], bet[8];
    {
        const float4 ga = __ldg(reinterpret_cast<const float4*>(g_stage.Gamma));
        const float4 gb = __ldg(reinterpret_cast<const float4*>(g_stage.Gamma + 4));
        const float4 ba = __ldg(reinterpret_cast<const float4*>(g_stage.Beta));
        const float4 bb = __ldg(reinterpret_cast<const float4*>(g_stage.Beta + 4));
        gam[0]=ga.x; gam[1]=ga.y; gam[2]=ga.z; gam[3]=ga.w;
        gam[4]=gb.x; gam[5]=gb.y; gam[6]=gb.z; gam[7]=gb.w;
        bet[0]=ba.x; bet[1]=ba.y; bet[2]=ba.z; bet[3]=ba.w;
        bet[4]=bb.x; bet[5]=bb.y; bet[6]=bb.z; bet[7]=bb.w;
    }

    // LN (full x with gamma/beta)
    float2 xd[8];
    {
        const float4* p = reinterpret_cast<const float4*>(m + gid * 8);
        float4 a0 = p[0];
        float4 a1 = p[1];
        float xr[8] = {a0.x, a0.y, a0.z, a0.w, a1.x, a1.y, a1.z, a1.w};
        float mean = 0.f;
#pragma unroll
        for (int c = 0; c < 8; c++) mean += xr[c];
        mean *= 0.125f;
        float var = 0.f;
#pragma unroll
        for (int c = 0; c < 8; c++) { float d = xr[c] - mean; var = fmaf(d, d, var); }
        var *= 0.125f;
        const float rstd = rsqrtf(var + LN_EPS);
#pragma unroll
        for (int c = 0; c < 8; c++)
            xd[c] = dup(fmaf((xr[c] - mean) * rstd, gam[c], bet[c]));
    }

    float2 whp[4];
    {
        const float4* pw = reinterpret_cast<const float4*>(&g_w[gid * 8]);
        const float4 wA = pw[0], wB = pw[1];
        const float4* pr = reinterpret_cast<const float4*>(&g_rcp[i * 8]);
        const float4 rA = __ldg(pr), rB = __ldg(pr + 1);
        whp[0] = mul2(lo2(wA), lo2(rA)); whp[1] = mul2(hi2(wA), hi2(rA));
        whp[2] = mul2(lo2(wB), lo2(rB)); whp[3] = mul2(hi2(wB), hi2(rB));
    }

    float2 v2[4];
#pragma unroll
    for (int cp = 0; cp < 4; cp++) {
        const float4 w0 = __ldg(Wv2p + cp * 4);
        const float4 w1 = __ldg(Wv2p + cp * 4 + 1);
        const float4 w2 = __ldg(Wv2p + cp * 4 + 2);
        const float4 w3 = __ldg(Wv2p + cp * 4 + 3);
        float2 a;
        PAIRDOT8(a, xd, w0, w1, w2, w3);
        v2[cp] = a;
    }

    float2 o2h[8];
#pragma unroll
    for (int co = 0; co < 8; co++) o2h[co] = make_float2(0.f, 0.f);

#pragma unroll
    for (int hp = 0; hp < 4; hp++) {
        const float2 wh = whp[hp];
#pragma unroll
        for (int c = 0; c < 8; c++) {
            const float4 ga = __ldg(Wg2p + (hp * 8 + c) * 4);
            const float4 gb = __ldg(Wg2p + (hp * 8 + c) * 4 + 1);
            const float4 gc = __ldg(Wg2p + (hp * 8 + c) * 4 + 2);
            const float4 gd = __ldg(Wg2p + (hp * 8 + c) * 4 + 3);
            float2 g2;
            PAIRDOT8(g2, xd, ga, gb, gc, gd);

            float2 t2 = make_float2(tanh_apx(g2.x), tanh_apx(g2.y));
            const float vc = (c & 1) ? v2[c >> 1].y : v2[c >> 1].x;
            const float2 hv = mul2(wh, dup(vc));
            const float2 coef = fma2(t2, hv, hv);

            const float4 u0 = __ldg(WoPp + (hp * 8 + c) * 4);
            const float4 u1 = __ldg(WoPp + (hp * 8 + c) * 4 + 1);
            const float4 u2 = __ldg(WoPp + (hp * 8 + c) * 4 + 2);
            const float4 u3 = __ldg(WoPp + (hp * 8 + c) * 4 + 3);
            o2h[0] = fma2(lo2(u0), coef, o2h[0]);
            o2h[1] = fma2(hi2(u0), coef, o2h[1]);
            o2h[2] = fma2(lo2(u1), coef, o2h[2]);
            o2h[3] = fma2(hi2(u1), coef, o2h[3]);
            o2h[4] = fma2(lo2(u2), coef, o2h[4]);
            o2h[5] = fma2(hi2(u2), coef, o2h[5]);
            o2h[6] = fma2(lo2(u3), coef, o2h[6]);
            o2h[7] = fma2(hi2(u3), coef, o2h[7]);
        }
    }

    float bo8[8];
    {
        const float4 boA = __ldg(reinterpret_cast<const float4*>(g_stage.Bo));
        const float4 boB = __ldg(reinterpret_cast<const float4*>(g_stage.Bo + 4));
        bo8[0]=boA.x; bo8[1]=boA.y; bo8[2]=boA.z; bo8[3]=boA.w;
        bo8[4]=boB.x; bo8[5]=boB.y; bo8[6]=boB.z; bo8[7]=boB.w;
    }
    float o[8];
#pragma unroll
    for (int co = 0; co < 8; co++) o[co] = (o2h[co].x + o2h[co].y) + bo8[co];

    float4* po = reinterpret_cast<float4*>(out + gid * 8);
    po[0] = make_float4(o[0], o[1], o[2], o[3]);
    po[1] = make_float4(o[4], o[5], o[6], o[7]);
}

extern "C" void kernel_launch(void* const* d_in, const int* in_sizes, int n_in,
                              void* d_out, int out_size) {
    (void)in_sizes; (void)n_in; (void)out_size;
    const float* m  = (const float*)d_in[0];
    float* out      = (float*)d_out;

    msa_attn_weights_kernel<<<I_DIM / CPG, A_THREADS>>>(
        m,
        (const float*)d_in[1], (const float*)d_in[2], (const float*)d_in[3],
        (const float*)d_in[4], (const float*)d_in[5], (const float*)d_in[6],
        (const float*)d_in[7], (const float*)d_in[8]);

    msa_stream_kernel<<<(S_DIM * I_DIM) / B_THREADS, B_THREADS>>>(m, out);
}

// round 17
// speedup vs baseline: 2.3177x; 2.3177x over previous
#include <cuda_runtime.h>
#include <cuda_fp16.h>

// MSAColumnGlobalAttention: B=1, s=1024, i=512, c=8, h=8
// R14 (proven 37.3us) + e' stored as fp16 (halves A-write / B-read traffic).
// Kernel A (4 cols/CTA, 512 thr, grid 128, coalesced): pass1 LN sums -> xbar
//   -> qk (gamma-folded); pass2 re-read m (L2-hot), e'=exp(xn.(gamma*qk))
//   stored as __half, 0.5/sum -> g_rcp. CTA0 repacks weights -> g_stage.
// memcpyToSymbol g_stage -> cw (LDCU uniform path is load-bearing; R16 proved
//   LDG weights catastrophic).
// Kernel B: R10 control math; e loaded as fp16 and converted.

#define LN_EPS 1e-5f
#define I_DIM 512
#define S_DIM 1024
#define A_THREADS 512
#define A_NWARP (A_THREADS / 32)
#define CPG 4                      // columns per CTA
#define NSTRAND (A_THREADS / CPG)  // 128 s-strands
#define ROWS_PT (S_DIM / NSTRAND)  // 8 rows per thread
#define QK_PAD 72
#define B_THREADS 256

struct WeightsB {
    float Wv2[64];
    float Wg2[512];   // pairs over h, PRE-SCALED by 0.5
    float WoP[512];   // pairs over h / co
    float Bo[8];
    float Gamma[8];
    float Beta[8];
};

__device__   WeightsB g_stage;
__constant__ WeightsB cw;
__device__   __half g_w[S_DIM * I_DIM * 8];   // e' = exp(xn.(gamma*qk)), fp16
__device__   float  g_rcp[I_DIM * 8];         // 0.5 / sum_t e'

// ---- f32x2 helpers ----
__device__ __forceinline__ float2 fma2(float2 a, float2 b, float2 c) {
    unsigned long long ra = *reinterpret_cast<unsigned long long*>(&a);
    unsigned long long rb = *reinterpret_cast<unsigned long long*>(&b);
    unsigned long long rc = *reinterpret_cast<unsigned long long*>(&c);
    unsigned long long rd;
    asm("fma.rn.f32x2 %0, %1, %2, %3;" : "=l"(rd) : "l"(ra), "l"(rb), "l"(rc));
    return *reinterpret_cast<float2*>(&rd);
}
__device__ __forceinline__ float2 mul2(float2 a, float2 b) {
    unsigned long long ra = *reinterpret_cast<unsigned long long*>(&a);
    unsigned long long rb = *reinterpret_cast<unsigned long long*>(&b);
    unsigned long long rd;
    asm("mul.rn.f32x2 %0, %1, %2;" : "=l"(rd) : "l"(ra), "l"(rb));
    return *reinterpret_cast<float2*>(&rd);
}
__device__ __forceinline__ float2 dup(float x) { return make_float2(x, x); }
__device__ __forceinline__ float2 lo2(float4 w) { return make_float2(w.x, w.y); }
__device__ __forceinline__ float2 hi2(float4 w) { return make_float2(w.z, w.w); }

__device__ __forceinline__ float tanh_apx(float x) {
    float y; asm("tanh.approx.f32 %0, %1;" : "=f"(y) : "f"(x)); return y;
}

#define PAIRDOT8(acc, xd, w0, w1, w2, w3)            \
    acc = mul2(xd[0], lo2(w0));                      \
    acc = fma2(xd[1], hi2(w0), acc);                 \
    acc = fma2(xd[2], lo2(w1), acc);                 \
    acc = fma2(xd[3], hi2(w1), acc);                 \
    acc = fma2(xd[4], lo2(w2), acc);                 \
    acc = fma2(xd[5], hi2(w2), acc);                 \
    acc = fma2(xd[6], lo2(w3), acc);                 \
    acc = fma2(xd[7], hi2(w3), acc);

// ============================ Kernel A ============================
__global__ __launch_bounds__(A_THREADS)
void msa_attn_weights_kernel(const float* __restrict__ m,
                             const float* __restrict__ gamma,
                             const float* __restrict__ beta,
                             const float* __restrict__ wq,
                             const float* __restrict__ wk,
                             const float* __restrict__ wv,
                             const float* __restrict__ wg,
                             const float* __restrict__ wo,
                             const float* __restrict__ bo)
{
    const int i0     = blockIdx.x * CPG;
    const int tid    = threadIdx.x;
    const int lane   = tid & 31;
    const int il     = tid & (CPG - 1);
    const int strand = tid >> 2;
    const int warp   = tid >> 5;
    const int i      = i0 + il;

    __shared__ float sWq[512];
    __shared__ float sWk[64];
    __shared__ float sRed[A_NWARP][CPG][8];
    __shared__ float sXbar[CPG][8];
    __shared__ float sQKg[CPG][QK_PAD];

    sWq[tid] = wq[tid];
    if (tid < 64) sWk[tid] = wk[tid];

    // CTA 0 repacks streaming weights (overlapped with other CTAs' work)
    if (blockIdx.x == 0) {
        const int row = tid >> 3, j = tid & 7;
        const int h = row >> 3, c = row & 7;
        g_stage.Wg2[((h >> 1) * 8 + c) * 16 + (j >> 1) * 4 + (j & 1) * 2 + (h & 1)] = 0.5f * wg[tid];
        const int co = tid >> 6, idx = tid & 63;
        const int hh = idx >> 3, cc = idx & 7;
        g_stage.WoP[(((hh >> 1) * 8 + cc) * 4 + (co >> 1)) * 4 + (co & 1) * 2 + (hh & 1)] = wo[tid];
        if (tid < 64) {
            const int c2 = tid >> 3, j2 = tid & 7;
            g_stage.Wv2[(c2 >> 1) * 16 + (j2 >> 1) * 4 + (j2 & 1) * 2 + (c2 & 1)] = wv[tid];
        }
        if (tid < 8) {
            g_stage.Bo[tid]    = bo[tid];
            g_stage.Gamma[tid] = gamma[tid];
            g_stage.Beta[tid]  = beta[tid];
        }
    }

    // ---- PASS 1: LN sums over this thread's 8 rows (xn transient) ----
    float acc[8];
#pragma unroll
    for (int c = 0; c < 8; c++) acc[c] = 0.f;

#pragma unroll
    for (int r = 0; r < ROWS_PT; r++) {
        const int s = strand + r * NSTRAND;
        const size_t gid = (size_t)s * I_DIM + i;
        const float4* p = reinterpret_cast<const float4*>(m + gid * 8);
        float4 a0 = p[0];
        float4 a1 = p[1];
        float xr[8] = {a0.x, a0.y, a0.z, a0.w, a1.x, a1.y, a1.z, a1.w};
        float mean = 0.f;
#pragma unroll
        for (int c = 0; c < 8; c++) mean += xr[c];
        mean *= 0.125f;
        float var = 0.f;
#pragma unroll
        for (int c = 0; c < 8; c++) { float d = xr[c] - mean; var = fmaf(d, d, var); }
        var *= 0.125f;
        const float rstd = rsqrtf(var + LN_EPS);
#pragma unroll
        for (int c = 0; c < 8; c++)
            acc[c] = fmaf(xr[c] - mean, rstd, acc[c]);
    }

    // reduce over strands sharing il within warp: shfl 4, 8, 16
#pragma unroll
    for (int c = 0; c < 8; c++) {
        acc[c] += __shfl_xor_sync(0xffffffffu, acc[c], 4);
        acc[c] += __shfl_xor_sync(0xffffffffu, acc[c], 8);
        acc[c] += __shfl_xor_sync(0xffffffffu, acc[c], 16);
    }
    if (lane < CPG) {
#pragma unroll
        for (int c = 0; c < 8; c++) sRed[warp][lane][c] = acc[c];
    }
    __syncthreads();
    if (tid < CPG * 8) {
        const int jl = tid >> 3, c = tid & 7;
        float s = sRed[0][jl][c];
#pragma unroll
        for (int w = 1; w < A_NWARP; w++) s += sRed[w][jl][c];
        sXbar[jl][c] = fmaf(__ldg(gamma + c), s, 1024.f * __ldg(beta + c));
    }
    __syncthreads();

    // qk for 4 columns: tid < 256 -> (il2, h, j)
    if (tid < CPG * 64) {
        const int il2 = tid >> 6;
        const int hj  = tid & 63;
        const int h = hj >> 3, j = hj & 7;
        float qk = 0.f;
#pragma unroll
        for (int c = 0; c < 8; c++) {
            float q = 0.f;
#pragma unroll
            for (int d = 0; d < 8; d++)
                q = fmaf(sXbar[il2][d], sWq[(h * 8 + c) * 8 + d], q);
            qk = fmaf(q, sWk[c * 8 + j], qk);
        }
        const float qscale = (1.f / 1024.f) * 0.35355339059327373f;
        sQKg[il2][h * 8 + j] = qk * qscale * __ldg(gamma + j);
    }
    __syncthreads();

    // ---- PASS 2: re-read m (L2-hot), recompute LN, e' -> fp16 store, sum ----
    float hred[8];
#pragma unroll
    for (int h = 0; h < 8; h++) hred[h] = 0.f;

#pragma unroll
    for (int r = 0; r < ROWS_PT; r++) {
        const int s = strand + r * NSTRAND;
        const size_t gid = (size_t)s * I_DIM + i;
        const float4* p = reinterpret_cast<const float4*>(m + gid * 8);
        float4 a0 = p[0];
        float4 a1 = p[1];
        float xn[8] = {a0.x, a0.y, a0.z, a0.w, a1.x, a1.y, a1.z, a1.w};
        float mean = 0.f;
#pragma unroll
        for (int c = 0; c < 8; c++) mean += xn[c];
        mean *= 0.125f;
        float var = 0.f;
#pragma unroll
        for (int c = 0; c < 8; c++) { float d = xn[c] - mean; var = fmaf(d, d, var); }
        var *= 0.125f;
        const float rstd = rsqrtf(var + LN_EPS);
#pragma unroll
        for (int c = 0; c < 8; c++)
            xn[c] = (xn[c] - mean) * rstd;

        float e[8];
#pragma unroll
        for (int h = 0; h < 8; h++) {
            const float4 qa = *reinterpret_cast<const float4*>(&sQKg[il][h * 8]);
            const float4 qb = *reinterpret_cast<const float4*>(&sQKg[il][h * 8 + 4]);
            float a = xn[0] * qa.x, b = xn[1] * qa.y;
            a = fmaf(xn[2], qa.z, a);  b = fmaf(xn[3], qa.w, b);
            a = fmaf(xn[4], qb.x, a);  b = fmaf(xn[5], qb.y, b);
            a = fmaf(xn[6], qb.z, a);  b = fmaf(xn[7], qb.w, b);
            e[h] = __expf(a + b);
            hred[h] += e[h];
        }
        // pack to fp16x8 = 16 bytes, single coalesced store
        __align__(16) __half2 eh[4];
#pragma unroll
        for (int p4 = 0; p4 < 4; p4++)
            eh[p4] = __floats2half2_rn(e[2 * p4], e[2 * p4 + 1]);
        *reinterpret_cast<float4*>(&g_w[gid * 8]) = *reinterpret_cast<float4*>(eh);
    }

#pragma unroll
    for (int h = 0; h < 8; h++) {
        hred[h] += __shfl_xor_sync(0xffffffffu, hred[h], 4);
        hred[h] += __shfl_xor_sync(0xffffffffu, hred[h], 8);
        hred[h] += __shfl_xor_sync(0xffffffffu, hred[h], 16);
    }
    if (lane < CPG) {
#pragma unroll
        for (int h = 0; h < 8; h++) sRed[warp][lane][h] = hred[h];
    }
    __syncthreads();
    if (tid < CPG * 8) {
        const int jl = tid >> 3, h = tid & 7;
        float s = sRed[0][jl][h];
#pragma unroll
        for (int w = 1; w < A_NWARP; w++) s += sRed[w][jl][h];
        g_rcp[(i0 + jl) * 8 + h] = __fdividef(0.5f, s);
    }
}

// ============================ Kernel B ============================
__global__ __launch_bounds__(B_THREADS, 4)
void msa_stream_kernel(const float* __restrict__ m,
                       float* __restrict__ out)
{
    const size_t gid = (size_t)blockIdx.x * B_THREADS + threadIdx.x;  // = s*512 + i
    const int i = (int)(gid & (I_DIM - 1));

    // LN (full x with gamma/beta)
    float2 xd[8];
    {
        const float4* p = reinterpret_cast<const float4*>(m + gid * 8);
        float4 a0 = p[0];
        float4 a1 = p[1];
        float xr[8] = {a0.x, a0.y, a0.z, a0.w, a1.x, a1.y, a1.z, a1.w};
        float mean = 0.f;
#pragma unroll
        for (int c = 0; c < 8; c++) mean += xr[c];
        mean *= 0.125f;
        float var = 0.f;
#pragma unroll
        for (int c = 0; c < 8; c++) { float d = xr[c] - mean; var = fmaf(d, d, var); }
        var *= 0.125f;
        const float rstd = rsqrtf(var + LN_EPS);
#pragma unroll
        for (int c = 0; c < 8; c++)
            xd[c] = dup(fmaf((xr[c] - mean) * rstd, cw.Gamma[c], cw.Beta[c]));
    }

    float2 whp[4];
    {
        __align__(16) __half2 eh[4];
        *reinterpret_cast<float4*>(eh) = *reinterpret_cast<const float4*>(&g_w[gid * 8]);
        const float4* pr = reinterpret_cast<const float4*>(&g_rcp[i * 8]);
        const float4 rA = __ldg(pr), rB = __ldg(pr + 1);
        whp[0] = mul2(__half22float2(eh[0]), lo2(rA));
        whp[1] = mul2(__half22float2(eh[1]), hi2(rA));
        whp[2] = mul2(__half22float2(eh[2]), lo2(rB));
        whp[3] = mul2(__half22float2(eh[3]), hi2(rB));
    }

    float2 v2[4];
#pragma unroll
    for (int cp = 0; cp < 4; cp++) {
        const float4* vp = reinterpret_cast<const float4*>(&cw.Wv2[cp * 16]);
        const float4 w0 = vp[0], w1 = vp[1], w2 = vp[2], w3 = vp[3];
        float2 a;
        PAIRDOT8(a, xd, w0, w1, w2, w3);
        v2[cp] = a;
    }

    float2 o2h[8];
#pragma unroll
    for (int co = 0; co < 8; co++) o2h[co] = make_float2(0.f, 0.f);

#pragma unroll
    for (int hp = 0; hp < 4; hp++) {
        const float2 wh = whp[hp];
#pragma unroll
        for (int c = 0; c < 8; c++) {
            const float4* gp = reinterpret_cast<const float4*>(&cw.Wg2[(hp * 8 + c) * 16]);
            const float4 ga = gp[0], gb = gp[1], gc = gp[2], gd = gp[3];
            float2 g2;
            PAIRDOT8(g2, xd, ga, gb, gc, gd);

            float2 t2 = make_float2(tanh_apx(g2.x), tanh_apx(g2.y));
            const float vc = (c & 1) ? v2[c >> 1].y : v2[c >> 1].x;
            const float2 hv = mul2(wh, dup(vc));
            const float2 coef = fma2(t2, hv, hv);

            const float4* op = reinterpret_cast<const float4*>(&cw.WoP[(hp * 8 + c) * 16]);
            const float4 u0 = op[0], u1 = op[1], u2 = op[2], u3 = op[3];
            o2h[0] = fma2(lo2(u0), coef, o2h[0]);
            o2h[1] = fma2(hi2(u0), coef, o2h[1]);
            o2h[2] = fma2(lo2(u1), coef, o2h[2]);
            o2h[3] = fma2(hi2(u1), coef, o2h[3]);
            o2h[4] = fma2(lo2(u2), coef, o2h[4]);
            o2h[5] = fma2(hi2(u2), coef, o2h[5]);
            o2h[6] = fma2(lo2(u3), coef, o2h[6]);
            o2h[7] = fma2(hi2(u3), coef, o2h[7]);
        }
    }

    float o[8];
#pragma unroll
    for (int co = 0; co < 8; co++) o[co] = (o2h[co].x + o2h[co].y) + cw.Bo[co];

    float4* po = reinterpret_cast<float4*>(out + gid * 8);
    po[0] = make_float4(o[0], o[1], o[2], o[3]);
    po[1] = make_float4(o[4], o[5], o[6], o[7]);
}

extern "C" void kernel_launch(void* const* d_in, const int* in_sizes, int n_in,
                              void* d_out, int out_size) {
    (void)in_sizes; (void)n_in; (void)out_size;
    const float* m  = (const float*)d_in[0];
    float* out      = (float*)d_out;

    msa_attn_weights_kernel<<<I_DIM / CPG, A_THREADS>>>(
        m,
        (const float*)d_in[1], (const float*)d_in[2], (const float*)d_in[3],
        (const float*)d_in[4], (const float*)d_in[5], (const float*)d_in[6],
        (const float*)d_in[7], (const float*)d_in[8]);

    void* pstage = nullptr;
    cudaGetSymbolAddress(&pstage, g_stage);
    cudaMemcpyToSymbolAsync(cw, pstage, sizeof(WeightsB), 0, cudaMemcpyDeviceToDevice, 0);

    msa_stream_kernel<<<(S_DIM * I_DIM) / B_THREADS, B_THREADS>>>(m, out);
}